// round 2
// baseline (speedup 1.0000x reference)
#include <cuda_runtime.h>
#include <cstdint>

#define IN_F   4096
#define OUT_F  4096
#define PACKED (IN_F / 2)
#define NBLK   (IN_F / 64)

#define BM 128
#define BN 128
#define BK 32
#define LDS_ (BK + 4)               // 36 floats: pads rows so fragment LDS are conflict-free
#define TILE_ELEMS (BM * LDS_)      // 4608 floats per tile buffer
#define NK (IN_F / BK)              // 128 k-tiles
#define SMEM_BYTES (2 * 2 * TILE_ELEMS * 4)  // 2 buffers x (A+B) = 73728 B

// Dequantized + tf32-rounded weight scratch: W[out, in] row-major (67 MB).
__device__ float g_Wdq[(size_t)OUT_F * IN_F];

// ---------------------------------------------------------------------------
// Kernel 1: dequantize packed 4-bit codes -> fp32 -> tf32-rounded bits.
// weight_packed[o][j] holds one byte: hi nibble -> element 2j, lo -> 2j+1.
// scale block index of element i is i/64 -> for pair (2j, 2j+1) it's j>>5.
// ---------------------------------------------------------------------------
__global__ void dequant_kernel(const int* __restrict__ wp,
                               const float* __restrict__ centroids,
                               const float* __restrict__ scales) {
    __shared__ float cent[16];
    if (threadIdx.x < 16) cent[threadIdx.x] = centroids[threadIdx.x];
    __syncthreads();

    int idx = blockIdx.x * blockDim.x + threadIdx.x;
    if (idx >= OUT_F * PACKED) return;
    int o = idx >> 11;          // / PACKED (2048)
    int j = idx & (PACKED - 1);

    int v = wp[idx] & 255;
    float s = scales[o * NBLK + (j >> 5)];
    float w0 = cent[(v >> 4) & 15] * s;
    float w1 = cent[v & 15] * s;

    uint32_t t0, t1;
    asm("cvt.rna.tf32.f32 %0, %1;" : "=r"(t0) : "f"(w0));
    asm("cvt.rna.tf32.f32 %0, %1;" : "=r"(t1) : "f"(w1));

    float2 out;
    out.x = __uint_as_float(t0);
    out.y = __uint_as_float(t1);
    *reinterpret_cast<float2*>(&g_Wdq[(size_t)o * IN_F + 2 * (size_t)j]) = out;
}

// ---------------------------------------------------------------------------
// Kernel 2: out[M, OUT] = x[M, IN] @ Wdq[OUT, IN]^T  via mma.sync tf32.
// Block tile 128x128x32, 8 warps (2 M x 4 N), warp tile 64x32.
// Double-buffered cp.async pipeline.
// ---------------------------------------------------------------------------
__device__ __forceinline__ void mma_tf32(float* c, const uint32_t* a, const uint32_t* b) {
    asm volatile(
        "mma.sync.aligned.m16n8k8.row.col.f32.tf32.tf32.f32 "
        "{%0,%1,%2,%3}, {%4,%5,%6,%7}, {%8,%9}, {%0,%1,%2,%3};\n"
        : "+f"(c[0]), "+f"(c[1]), "+f"(c[2]), "+f"(c[3])
        : "r"(a[0]), "r"(a[1]), "r"(a[2]), "r"(a[3]),
          "r"(b[0]), "r"(b[1]));
}

__device__ __forceinline__ void load_tiles(uint32_t sA, uint32_t sB,
                                           const float* Ag, const float* Bg,
                                           int kt, int buf, int row0, int colf) {
#pragma unroll
    for (int i = 0; i < 4; i++) {
        int r = row0 + i * 32;
        uint32_t da = sA + (uint32_t)((buf * TILE_ELEMS + r * LDS_ + colf) * 4);
        const float* pa = Ag + (size_t)r * IN_F + (size_t)kt * BK + colf;
        asm volatile("cp.async.cg.shared.global [%0], [%1], 16;\n" :: "r"(da), "l"(pa));
        uint32_t db = sB + (uint32_t)((buf * TILE_ELEMS + r * LDS_ + colf) * 4);
        const float* pb = Bg + (size_t)r * IN_F + (size_t)kt * BK + colf;
        asm volatile("cp.async.cg.shared.global [%0], [%1], 16;\n" :: "r"(db), "l"(pb));
    }
}

__global__ void __launch_bounds__(256, 2)
gemm_tf32_kernel(const float* __restrict__ X, float* __restrict__ Out) {
    extern __shared__ float smem[];
    float* As = smem;                      // 2 * TILE_ELEMS
    float* Bs = smem + 2 * TILE_ELEMS;     // 2 * TILE_ELEMS

    const int tid  = threadIdx.x;
    const int warp = tid >> 5;
    const int lane = tid & 31;
    const int wm = warp >> 2;              // 0..1 -> M offset wm*64
    const int wn = warp & 3;               // 0..3 -> N offset wn*32

    const int bm = blockIdx.y * BM;
    const int bn = blockIdx.x * BN;

    const float* Ag = X + (size_t)bm * IN_F;
    const float* Bg = g_Wdq + (size_t)bn * IN_F;

    // global->smem mapping: 256 threads x 4 chunks of 16B cover 128 rows x 32 floats
    const int row0 = tid >> 3;             // 0..31, +i*32
    const int colf = (tid & 7) * 4;        // 0,4,...,28

    const uint32_t sA = (uint32_t)__cvta_generic_to_shared(As);
    const uint32_t sB = (uint32_t)__cvta_generic_to_shared(Bs);

    float c[4][4][4];
#pragma unroll
    for (int i = 0; i < 4; i++)
#pragma unroll
        for (int j = 0; j < 4; j++)
#pragma unroll
            for (int k = 0; k < 4; k++) c[i][j][k] = 0.0f;

    // prologue: tile 0 -> buffer 0
    load_tiles(sA, sB, Ag, Bg, 0, 0, row0, colf);
    asm volatile("cp.async.commit_group;\n" ::: "memory");

    for (int kt = 0; kt < NK; kt++) {
        if (kt + 1 < NK)
            load_tiles(sA, sB, Ag, Bg, kt + 1, (kt + 1) & 1, row0, colf);
        asm volatile("cp.async.commit_group;\n" ::: "memory");
        asm volatile("cp.async.wait_group 1;\n" ::: "memory");
        __syncthreads();

        const float* A0 = As + (kt & 1) * TILE_ELEMS;
        const float* B0 = Bs + (kt & 1) * TILE_ELEMS;

#pragma unroll
        for (int kk = 0; kk < BK; kk += 8) {
            uint32_t a[4][4];
            uint32_t b[4][2];
            const int ar = wm * 64 + (lane >> 2);
            const int ac = kk + (lane & 3);
#pragma unroll
            for (int ma = 0; ma < 4; ma++) {
                float f0 = A0[(ar + ma * 16) * LDS_ + ac];
                float f1 = A0[(ar + ma * 16 + 8) * LDS_ + ac];
                float f2 = A0[(ar + ma * 16) * LDS_ + ac + 4];
                float f3 = A0[(ar + ma * 16 + 8) * LDS_ + ac + 4];
                asm("cvt.rna.tf32.f32 %0, %1;" : "=r"(a[ma][0]) : "f"(f0));
                asm("cvt.rna.tf32.f32 %0, %1;" : "=r"(a[ma][1]) : "f"(f1));
                asm("cvt.rna.tf32.f32 %0, %1;" : "=r"(a[ma][2]) : "f"(f2));
                asm("cvt.rna.tf32.f32 %0, %1;" : "=r"(a[ma][3]) : "f"(f3));
            }
            const int br = wn * 32 + (lane >> 2);
            const int bc = kk + (lane & 3);
#pragma unroll
            for (int nb = 0; nb < 4; nb++) {
                b[nb][0] = __float_as_uint(B0[(br + nb * 8) * LDS_ + bc]);      // pre-rounded tf32
                b[nb][1] = __float_as_uint(B0[(br + nb * 8) * LDS_ + bc + 4]);
            }
#pragma unroll
            for (int ma = 0; ma < 4; ma++)
#pragma unroll
                for (int nb = 0; nb < 4; nb++)
                    mma_tf32(c[ma][nb], a[ma], b[nb]);
        }
        __syncthreads();
    }

    // epilogue
    float* Og = Out + (size_t)bm * OUT_F + bn;
#pragma unroll
    for (int ma = 0; ma < 4; ma++) {
#pragma unroll
        for (int nb = 0; nb < 4; nb++) {
            int r  = wm * 64 + ma * 16 + (lane >> 2);
            int cc = wn * 32 + nb * 8 + 2 * (lane & 3);
            *reinterpret_cast<float2*>(&Og[(size_t)r * OUT_F + cc]) =
                make_float2(c[ma][nb][0], c[ma][nb][1]);
            *reinterpret_cast<float2*>(&Og[(size_t)(r + 8) * OUT_F + cc]) =
                make_float2(c[ma][nb][2], c[ma][nb][3]);
        }
    }
}

// ---------------------------------------------------------------------------
extern "C" void kernel_launch(void* const* d_in, const int* in_sizes, int n_in,
                              void* d_out, int out_size) {
    const float* x       = (const float*)d_in[0];   // [M, 4096] fp32 (flattened B*S)
    const int*   wp      = (const int*)d_in[1];     // [4096, 2048] int32 (byte values)
    const float* cent    = (const float*)d_in[2];   // [16] fp32
    const float* scales  = (const float*)d_in[3];   // [4096, 64] fp32
    float* out = (float*)d_out;

    const int M = in_sizes[0] / IN_F;               // 8192

    // 1) dequantize weights into device scratch (re-run each call; deterministic)
    int total = OUT_F * PACKED;
    dequant_kernel<<<(total + 255) / 256, 256>>>(wp, cent, scales);

    // 2) GEMM
    cudaFuncSetAttribute(gemm_tf32_kernel,
                         cudaFuncAttributeMaxDynamicSharedMemorySize, SMEM_BYTES);
    dim3 grid(OUT_F / BN, M / BM);                  // (32, 64)
    gemm_tf32_kernel<<<grid, 256, SMEM_BYTES>>>(x, out);
}

// round 4
// speedup vs baseline: 1.0791x; 1.0791x over previous
#include <cuda_runtime.h>
#include <cstdint>

#define IN_F   4096
#define OUT_F  4096
#define PACKED (IN_F / 2)
#define NBLK   (IN_F / 64)

#define BM 128
#define BN 128
#define BK 32
#define LDS_ (BK + 4)               // 36 floats: pads rows so fragment LDS are conflict-free
#define TILE_ELEMS (BM * LDS_)      // 4608 floats per tile buffer
#define NK (IN_F / BK)              // 128 k-tiles
#define STAGES 3
#define SMEM_BYTES (STAGES * 2 * TILE_ELEMS * 4)  // 3 stages x (A+B) = 110592 B

// Pre-rounded tf32 operand scratch (row-major, same layout as sources).
__device__ float g_Wdq[(size_t)OUT_F * IN_F];   // 67 MB
__device__ float g_Xdq[(size_t)8192 * IN_F];    // 134 MB

// ---------------------------------------------------------------------------
// Pre-pass 1: dequantize packed 4-bit codes -> fp32 -> tf32-rounded bits.
// ---------------------------------------------------------------------------
__global__ void dequant_kernel(const int* __restrict__ wp,
                               const float* __restrict__ centroids,
                               const float* __restrict__ scales) {
    __shared__ float cent[16];
    if (threadIdx.x < 16) cent[threadIdx.x] = centroids[threadIdx.x];
    __syncthreads();

    int idx = blockIdx.x * blockDim.x + threadIdx.x;
    if (idx >= OUT_F * PACKED) return;
    int o = idx >> 11;          // / PACKED (2048)
    int j = idx & (PACKED - 1);

    int v = wp[idx] & 255;
    float s = scales[o * NBLK + (j >> 5)];
    float w0 = cent[(v >> 4) & 15] * s;
    float w1 = cent[v & 15] * s;

    uint32_t t0, t1;
    asm("cvt.rna.tf32.f32 %0, %1;" : "=r"(t0) : "f"(w0));
    asm("cvt.rna.tf32.f32 %0, %1;" : "=r"(t1) : "f"(w1));

    float2 out;
    out.x = __uint_as_float(t0);
    out.y = __uint_as_float(t1);
    *reinterpret_cast<float2*>(&g_Wdq[(size_t)o * IN_F + 2 * (size_t)j]) = out;
}

// ---------------------------------------------------------------------------
// Pre-pass 2: round X to tf32 bits (removes all cvts from the GEMM mainloop).
// ---------------------------------------------------------------------------
__global__ void round_x_kernel(const float* __restrict__ X, int total4) {
    int t = blockIdx.x * blockDim.x + threadIdx.x;
    if (t >= total4) return;
    float4 v = reinterpret_cast<const float4*>(X)[t];
    uint32_t t0, t1, t2, t3;
    asm("cvt.rna.tf32.f32 %0, %1;" : "=r"(t0) : "f"(v.x));
    asm("cvt.rna.tf32.f32 %0, %1;" : "=r"(t1) : "f"(v.y));
    asm("cvt.rna.tf32.f32 %0, %1;" : "=r"(t2) : "f"(v.z));
    asm("cvt.rna.tf32.f32 %0, %1;" : "=r"(t3) : "f"(v.w));
    float4 o;
    o.x = __uint_as_float(t0); o.y = __uint_as_float(t1);
    o.z = __uint_as_float(t2); o.w = __uint_as_float(t3);
    reinterpret_cast<float4*>(g_Xdq)[t] = o;
}

// ---------------------------------------------------------------------------
// GEMM: out[M, OUT] = Xdq[M, IN] @ Wdq[OUT, IN]^T  via mma.sync tf32.
// Block tile 128x128x32, 8 warps (2 M x 4 N), warp tile 64x32.
// 3-stage cp.async pipeline, pre-rounded operands (no in-loop cvt).
// ---------------------------------------------------------------------------
__device__ __forceinline__ void mma_tf32(float* c, const uint32_t* a, const uint32_t* b) {
    asm volatile(
        "mma.sync.aligned.m16n8k8.row.col.f32.tf32.tf32.f32 "
        "{%0,%1,%2,%3}, {%4,%5,%6,%7}, {%8,%9}, {%0,%1,%2,%3};\n"
        : "+f"(c[0]), "+f"(c[1]), "+f"(c[2]), "+f"(c[3])
        : "r"(a[0]), "r"(a[1]), "r"(a[2]), "r"(a[3]),
          "r"(b[0]), "r"(b[1]));
}

__device__ __forceinline__ void load_tiles(uint32_t sA, uint32_t sB,
                                           const float* Ag, const float* Bg,
                                           int kt, int buf, int row0, int colf) {
#pragma unroll
    for (int i = 0; i < 4; i++) {
        int r = row0 + i * 32;
        uint32_t da = sA + (uint32_t)((buf * TILE_ELEMS + r * LDS_ + colf) * 4);
        const float* pa = Ag + (size_t)r * IN_F + (size_t)kt * BK + colf;
        asm volatile("cp.async.cg.shared.global [%0], [%1], 16;\n" :: "r"(da), "l"(pa));
        uint32_t db = sB + (uint32_t)((buf * TILE_ELEMS + r * LDS_ + colf) * 4);
        const float* pb = Bg + (size_t)r * IN_F + (size_t)kt * BK + colf;
        asm volatile("cp.async.cg.shared.global [%0], [%1], 16;\n" :: "r"(db), "l"(pb));
    }
}

__global__ void __launch_bounds__(256, 2)
gemm_tf32_kernel(float* __restrict__ Out) {
    extern __shared__ float smem[];
    float* As = smem;                          // STAGES * TILE_ELEMS
    float* Bs = smem + STAGES * TILE_ELEMS;    // STAGES * TILE_ELEMS

    const int tid  = threadIdx.x;
    const int warp = tid >> 5;
    const int lane = tid & 31;
    const int wm = warp >> 2;              // 0..1 -> M offset wm*64
    const int wn = warp & 3;               // 0..3 -> N offset wn*32

    const int bm = blockIdx.y * BM;
    const int bn = blockIdx.x * BN;

    const float* Ag = g_Xdq + (size_t)bm * IN_F;
    const float* Bg = g_Wdq + (size_t)bn * IN_F;

    // global->smem mapping: 256 threads x 4 chunks of 16B cover 128 rows x 32 floats
    const int row0 = tid >> 3;             // 0..31, +i*32
    const int colf = (tid & 7) * 4;        // 0,4,...,28

    const uint32_t sA = (uint32_t)__cvta_generic_to_shared(As);
    const uint32_t sB = (uint32_t)__cvta_generic_to_shared(Bs);

    float c[4][4][4];
#pragma unroll
    for (int i = 0; i < 4; i++)
#pragma unroll
        for (int j = 0; j < 4; j++)
#pragma unroll
            for (int k = 0; k < 4; k++) c[i][j][k] = 0.0f;

    // prologue: tiles 0,1 -> buffers 0,1
    load_tiles(sA, sB, Ag, Bg, 0, 0, row0, colf);
    asm volatile("cp.async.commit_group;\n" ::: "memory");
    load_tiles(sA, sB, Ag, Bg, 1, 1, row0, colf);
    asm volatile("cp.async.commit_group;\n" ::: "memory");

    const int ar = wm * 64 + (lane >> 2);
    const int br = wn * 32 + (lane >> 2);
    const int acq = lane & 3;

    for (int kt = 0; kt < NK; kt++) {
        asm volatile("cp.async.wait_group 1;\n" ::: "memory");
        __syncthreads();

        // issue next-next tile load before computing (overlap with HMMA)
        if (kt + 2 < NK) {
            load_tiles(sA, sB, Ag, Bg, kt + 2, (kt + 2) % STAGES, row0, colf);
        }
        asm volatile("cp.async.commit_group;\n" ::: "memory");

        const float* A0 = As + (kt % STAGES) * TILE_ELEMS;
        const float* B0 = Bs + (kt % STAGES) * TILE_ELEMS;

#pragma unroll
        for (int kk = 0; kk < BK; kk += 8) {
            uint32_t a[4][4];
            uint32_t b[4][2];
            const int ac = kk + acq;
#pragma unroll
            for (int ma = 0; ma < 4; ma++) {
                a[ma][0] = __float_as_uint(A0[(ar + ma * 16) * LDS_ + ac]);
                a[ma][1] = __float_as_uint(A0[(ar + ma * 16 + 8) * LDS_ + ac]);
                a[ma][2] = __float_as_uint(A0[(ar + ma * 16) * LDS_ + ac + 4]);
                a[ma][3] = __float_as_uint(A0[(ar + ma * 16 + 8) * LDS_ + ac + 4]);
            }
#pragma unroll
            for (int nb = 0; nb < 4; nb++) {
                b[nb][0] = __float_as_uint(B0[(br + nb * 8) * LDS_ + ac]);
                b[nb][1] = __float_as_uint(B0[(br + nb * 8) * LDS_ + ac + 4]);
            }
#pragma unroll
            for (int ma = 0; ma < 4; ma++)
#pragma unroll
                for (int nb = 0; nb < 4; nb++)
                    mma_tf32(c[ma][nb], a[ma], b[nb]);
        }
        __syncthreads();
    }

    // epilogue
    float* Og = Out + (size_t)bm * OUT_F + bn;
#pragma unroll
    for (int ma = 0; ma < 4; ma++) {
#pragma unroll
        for (int nb = 0; nb < 4; nb++) {
            int r  = wm * 64 + ma * 16 + (lane >> 2);
            int cc = wn * 32 + nb * 8 + 2 * (lane & 3);
            *reinterpret_cast<float2*>(&Og[(size_t)r * OUT_F + cc]) =
                make_float2(c[ma][nb][0], c[ma][nb][1]);
            *reinterpret_cast<float2*>(&Og[(size_t)(r + 8) * OUT_F + cc]) =
                make_float2(c[ma][nb][2], c[ma][nb][3]);
        }
    }
}

// ---------------------------------------------------------------------------
extern "C" void kernel_launch(void* const* d_in, const int* in_sizes, int n_in,
                              void* d_out, int out_size) {
    const float* x      = (const float*)d_in[0];   // [M, 4096] fp32
    const int*   wp     = (const int*)d_in[1];     // [4096, 2048] int32 bytes
    const float* cent   = (const float*)d_in[2];   // [16]
    const float* scales = (const float*)d_in[3];   // [4096, 64]
    float* out = (float*)d_out;

    const int M = in_sizes[0] / IN_F;              // 8192

    // 1) dequantize + tf32-round W
    int totalW = OUT_F * PACKED;
    dequant_kernel<<<(totalW + 255) / 256, 256>>>(wp, cent, scales);

    // 2) tf32-round X
    int totalX4 = M * (IN_F / 4);
    round_x_kernel<<<(totalX4 + 255) / 256, 256>>>(x, totalX4);

    // 3) GEMM
    cudaFuncSetAttribute(gemm_tf32_kernel,
                         cudaFuncAttributeMaxDynamicSharedMemorySize, SMEM_BYTES);
    dim3 grid(OUT_F / BN, M / BM);                 // (32, 64)
    gemm_tf32_kernel<<<grid, 256, SMEM_BYTES>>>(out);
}

// round 5
// speedup vs baseline: 1.1174x; 1.0355x over previous
#include <cuda_runtime.h>
#include <cstdint>

#define IN_F   4096
#define OUT_F  4096
#define PACKED (IN_F / 2)
#define NBLK   (IN_F / 64)

#define BM 128
#define BN 128
#define BK 32
#define LDS_ (BK + 4)               // 36 floats: fragment LDS conflict-free
#define TILE_ELEMS (BM * LDS_)      // 4608 floats per tile buffer
#define NK (IN_F / BK)              // 128 k-tiles
#define STAGES 3
#define SMEM_BYTES (STAGES * 2 * TILE_ELEMS * 4)  // 110592 B -> 2 CTA/SM

// Pre-rounded tf32 operand scratch (row-major, same layout as sources).
__device__ float g_Wdq[(size_t)OUT_F * IN_F];   // 67 MB
__device__ float g_Xdq[(size_t)8192 * IN_F];    // 134 MB

// ---------------------------------------------------------------------------
// Pre-pass 1: dequantize packed 4-bit codes -> fp32 -> tf32-rounded bits.
// ---------------------------------------------------------------------------
__global__ void dequant_kernel(const int* __restrict__ wp,
                               const float* __restrict__ centroids,
                               const float* __restrict__ scales) {
    __shared__ float cent[16];
    if (threadIdx.x < 16) cent[threadIdx.x] = centroids[threadIdx.x];
    __syncthreads();

    int idx = blockIdx.x * blockDim.x + threadIdx.x;
    if (idx >= OUT_F * PACKED) return;
    int o = idx >> 11;          // / PACKED (2048)
    int j = idx & (PACKED - 1);

    int v = wp[idx] & 255;
    float s = scales[o * NBLK + (j >> 5)];
    float w0 = cent[(v >> 4) & 15] * s;
    float w1 = cent[v & 15] * s;

    uint32_t t0, t1;
    asm("cvt.rna.tf32.f32 %0, %1;" : "=r"(t0) : "f"(w0));
    asm("cvt.rna.tf32.f32 %0, %1;" : "=r"(t1) : "f"(w1));

    float2 out;
    out.x = __uint_as_float(t0);
    out.y = __uint_as_float(t1);
    *reinterpret_cast<float2*>(&g_Wdq[(size_t)o * IN_F + 2 * (size_t)j]) = out;
}

// ---------------------------------------------------------------------------
// Pre-pass 2: round X to tf32 bits (no cvts in the GEMM mainloop).
// ---------------------------------------------------------------------------
__global__ void round_x_kernel(const float* __restrict__ X, int total4) {
    int t = blockIdx.x * blockDim.x + threadIdx.x;
    if (t >= total4) return;
    float4 v = reinterpret_cast<const float4*>(X)[t];
    uint32_t t0, t1, t2, t3;
    asm("cvt.rna.tf32.f32 %0, %1;" : "=r"(t0) : "f"(v.x));
    asm("cvt.rna.tf32.f32 %0, %1;" : "=r"(t1) : "f"(v.y));
    asm("cvt.rna.tf32.f32 %0, %1;" : "=r"(t2) : "f"(v.z));
    asm("cvt.rna.tf32.f32 %0, %1;" : "=r"(t3) : "f"(v.w));
    float4 o;
    o.x = __uint_as_float(t0); o.y = __uint_as_float(t1);
    o.z = __uint_as_float(t2); o.w = __uint_as_float(t3);
    reinterpret_cast<float4*>(g_Xdq)[t] = o;
}

// ---------------------------------------------------------------------------
// GEMM: out = Xdq @ Wdq^T via mma.sync tf32.
// Block 128x128x32, 4 warps (2x2), warp tile 64x64 (halves smem fragment
// traffic vs 64x32: A read 2x, B read 2x -> 64KB/tile < crossbar budget).
// 3-stage cp.async pipeline.
// ---------------------------------------------------------------------------
__device__ __forceinline__ void mma_tf32(float* c, const uint32_t* a, const uint32_t* b) {
    asm volatile(
        "mma.sync.aligned.m16n8k8.row.col.f32.tf32.tf32.f32 "
        "{%0,%1,%2,%3}, {%4,%5,%6,%7}, {%8,%9}, {%0,%1,%2,%3};\n"
        : "+f"(c[0]), "+f"(c[1]), "+f"(c[2]), "+f"(c[3])
        : "r"(a[0]), "r"(a[1]), "r"(a[2]), "r"(a[3]),
          "r"(b[0]), "r"(b[1]));
}

__device__ __forceinline__ void load_tiles(uint32_t sA, uint32_t sB,
                                           const float* Ag, const float* Bg,
                                           int kt, int buf, int row0, int colf) {
#pragma unroll
    for (int i = 0; i < 8; i++) {
        int r = row0 + i * 16;
        uint32_t da = sA + (uint32_t)((buf * TILE_ELEMS + r * LDS_ + colf) * 4);
        const float* pa = Ag + (size_t)r * IN_F + (size_t)kt * BK + colf;
        asm volatile("cp.async.cg.shared.global [%0], [%1], 16;\n" :: "r"(da), "l"(pa));
        uint32_t db = sB + (uint32_t)((buf * TILE_ELEMS + r * LDS_ + colf) * 4);
        const float* pb = Bg + (size_t)r * IN_F + (size_t)kt * BK + colf;
        asm volatile("cp.async.cg.shared.global [%0], [%1], 16;\n" :: "r"(db), "l"(pb));
    }
}

__global__ void __launch_bounds__(128, 2)
gemm_tf32_kernel(float* __restrict__ Out) {
    extern __shared__ float smem[];
    float* As = smem;                          // STAGES * TILE_ELEMS
    float* Bs = smem + STAGES * TILE_ELEMS;    // STAGES * TILE_ELEMS

    const int tid  = threadIdx.x;
    const int warp = tid >> 5;
    const int lane = tid & 31;
    const int wm = warp >> 1;              // 0..1 -> M offset wm*64
    const int wn = warp & 1;               // 0..1 -> N offset wn*64

    const int bm = blockIdx.y * BM;
    const int bn = blockIdx.x * BN;

    const float* Ag = g_Xdq + (size_t)bm * IN_F;
    const float* Bg = g_Wdq + (size_t)bn * IN_F;

    // global->smem mapping: 128 threads x 8 chunks of 16B cover 128 rows x 32 floats
    const int row0 = tid >> 3;             // 0..15, +i*16
    const int colf = (tid & 7) * 4;        // 0,4,...,28

    const uint32_t sA = (uint32_t)__cvta_generic_to_shared(As);
    const uint32_t sB = (uint32_t)__cvta_generic_to_shared(Bs);

    float c[4][8][4];
#pragma unroll
    for (int i = 0; i < 4; i++)
#pragma unroll
        for (int j = 0; j < 8; j++)
#pragma unroll
            for (int k = 0; k < 4; k++) c[i][j][k] = 0.0f;

    // prologue: tiles 0,1 -> buffers 0,1
    load_tiles(sA, sB, Ag, Bg, 0, 0, row0, colf);
    asm volatile("cp.async.commit_group;\n" ::: "memory");
    load_tiles(sA, sB, Ag, Bg, 1, 1, row0, colf);
    asm volatile("cp.async.commit_group;\n" ::: "memory");

    const int ar = wm * 64 + (lane >> 2);
    const int br = wn * 64 + (lane >> 2);
    const int acq = lane & 3;

    for (int kt = 0; kt < NK; kt++) {
        asm volatile("cp.async.wait_group 1;\n" ::: "memory");
        __syncthreads();

        if (kt + 2 < NK) {
            load_tiles(sA, sB, Ag, Bg, kt + 2, (kt + 2) % STAGES, row0, colf);
        }
        asm volatile("cp.async.commit_group;\n" ::: "memory");

        const float* A0 = As + (kt % STAGES) * TILE_ELEMS;
        const float* B0 = Bs + (kt % STAGES) * TILE_ELEMS;

#pragma unroll
        for (int kk = 0; kk < BK; kk += 8) {
            uint32_t a[4][4];
            uint32_t b[8][2];
            const int ac = kk + acq;
#pragma unroll
            for (int ma = 0; ma < 4; ma++) {
                a[ma][0] = __float_as_uint(A0[(ar + ma * 16) * LDS_ + ac]);
                a[ma][1] = __float_as_uint(A0[(ar + ma * 16 + 8) * LDS_ + ac]);
                a[ma][2] = __float_as_uint(A0[(ar + ma * 16) * LDS_ + ac + 4]);
                a[ma][3] = __float_as_uint(A0[(ar + ma * 16 + 8) * LDS_ + ac + 4]);
            }
#pragma unroll
            for (int nb = 0; nb < 8; nb++) {
                b[nb][0] = __float_as_uint(B0[(br + nb * 8) * LDS_ + ac]);
                b[nb][1] = __float_as_uint(B0[(br + nb * 8) * LDS_ + ac + 4]);
            }
#pragma unroll
            for (int ma = 0; ma < 4; ma++)
#pragma unroll
                for (int nb = 0; nb < 8; nb++)
                    mma_tf32(c[ma][nb], a[ma], b[nb]);
        }
        __syncthreads();
    }

    // epilogue
    float* Og = Out + (size_t)bm * OUT_F + bn;
#pragma unroll
    for (int ma = 0; ma < 4; ma++) {
#pragma unroll
        for (int nb = 0; nb < 8; nb++) {
            int r  = wm * 64 + ma * 16 + (lane >> 2);
            int cc = wn * 64 + nb * 8 + 2 * (lane & 3);
            *reinterpret_cast<float2*>(&Og[(size_t)r * OUT_F + cc]) =
                make_float2(c[ma][nb][0], c[ma][nb][1]);
            *reinterpret_cast<float2*>(&Og[(size_t)(r + 8) * OUT_F + cc]) =
                make_float2(c[ma][nb][2], c[ma][nb][3]);
        }
    }
}

// ---------------------------------------------------------------------------
extern "C" void kernel_launch(void* const* d_in, const int* in_sizes, int n_in,
                              void* d_out, int out_size) {
    const float* x      = (const float*)d_in[0];   // [M, 4096] fp32
    const int*   wp     = (const int*)d_in[1];     // [4096, 2048] int32 bytes
    const float* cent   = (const float*)d_in[2];   // [16]
    const float* scales = (const float*)d_in[3];   // [4096, 64]
    float* out = (float*)d_out;

    const int M = in_sizes[0] / IN_F;              // 8192

    int totalW = OUT_F * PACKED;
    dequant_kernel<<<(totalW + 255) / 256, 256>>>(wp, cent, scales);

    int totalX4 = M * (IN_F / 4);
    round_x_kernel<<<(totalX4 + 255) / 256, 256>>>(x, totalX4);

    cudaFuncSetAttribute(gemm_tf32_kernel,
                         cudaFuncAttributeMaxDynamicSharedMemorySize, SMEM_BYTES);
    dim3 grid(OUT_F / BN, M / BM);                 // (32, 64)
    gemm_tf32_kernel<<<grid, 128, SMEM_BYTES>>>(out);
}

// round 6
// speedup vs baseline: 1.4045x; 1.2569x over previous
#include <cuda_runtime.h>
#include <cstdint>

#define IN_F   4096
#define OUT_F  4096
#define PACKED (IN_F / 2)
#define NBLK   (IN_F / 64)

#define BM 128
#define BN 128
#define BK 32
#define NKT (IN_F / BK)             // 128 k-tiles
#define TILE_FLOATS 4096            // 128x32 floats = 16 KB (fragment-ordered)
#define A_TILE_BYTES 16384
#define B_TILE_BYTES 16384
#define STAGE_BYTES  32768
#define STAGES 3
#define SMEM_BYTES (STAGES * STAGE_BYTES)   // 98304 B -> 2 CTA/SM

// Fragment-ordered, tf32-pre-rounded operand scratch.
// A tile (128x32): float idx = ((kk*8 + mf)*32 + lane)*4 + slot
//   lane = (rr&7)*4 + c,  slot = (rr>>3) + 2*hi,  where m'=mf*16+rr, k'=kk*8+hi*4+c
// B tile (128x32): float idx = ((kk*16 + nf)*32 + lane)*2 + hi
//   lane = (n'&7)*4 + c,  where n'=nf*8+(n'&7), k'=kk*8+hi*4+c
__device__ float g_At[(size_t)(8192 / BM) * NKT * TILE_FLOATS];   // 134 MB
__device__ float g_Bt[(size_t)(OUT_F / BN) * NKT * TILE_FLOATS];  //  67 MB

// ---------------------------------------------------------------------------
// Pre-pass 1: dequantize 4-bit codes -> tf32 bits -> fragment-ordered g_Bt.
// ---------------------------------------------------------------------------
__global__ void dequant_kernel(const int* __restrict__ wp,
                               const float* __restrict__ centroids,
                               const float* __restrict__ scales) {
    __shared__ float cent[16];
    if (threadIdx.x < 16) cent[threadIdx.x] = centroids[threadIdx.x];
    __syncthreads();

    int idx = blockIdx.x * blockDim.x + threadIdx.x;
    if (idx >= OUT_F * PACKED) return;
    int o = idx >> 11;              // / 2048
    int j = idx & (PACKED - 1);

    int v = wp[idx] & 255;
    float s = scales[o * NBLK + (j >> 5)];
    float w0 = cent[(v >> 4) & 15] * s;   // element k0 = 2j
    float w1 = cent[v & 15] * s;          // element k0+1

    uint32_t t0, t1;
    asm("cvt.rna.tf32.f32 %0, %1;" : "=r"(t0) : "f"(w0));
    asm("cvt.rna.tf32.f32 %0, %1;" : "=r"(t1) : "f"(w1));

    int k0 = 2 * j;
    int ntile = o >> 7;             // / BN
    int np = o & 127;
    int kt = k0 >> 5;
    int kp = k0 & 31;
    int kk = kp >> 3;
    int q  = kp & 7;
    int c  = q & 3;                 // even (0 or 2)
    int hi = q >> 2;
    int nf = np >> 3;
    int lane = (np & 7) * 4 + c;

    float* tile = g_Bt + (size_t)ntile * (NKT * TILE_FLOATS) + (size_t)kt * TILE_FLOATS;
    int f0 = ((kk * 16 + nf) * 32 + lane) * 2 + hi;
    tile[f0]     = __uint_as_float(t0);
    tile[f0 + 2] = __uint_as_float(t1);   // c+1 -> lane+1 -> +2 floats
}

// ---------------------------------------------------------------------------
// Pre-pass 2: tf32-round X -> fragment-ordered g_At.
// ---------------------------------------------------------------------------
__global__ void retile_x_kernel(const float* __restrict__ X, int M) {
    int t = blockIdx.x * blockDim.x + threadIdx.x;
    if (t >= M * (IN_F / 4)) return;
    int e = t * 4;
    int m = e >> 12;
    int i = e & (IN_F - 1);

    float4 v = *reinterpret_cast<const float4*>(X + (size_t)m * IN_F + i);
    uint32_t t0, t1, t2, t3;
    asm("cvt.rna.tf32.f32 %0, %1;" : "=r"(t0) : "f"(v.x));
    asm("cvt.rna.tf32.f32 %0, %1;" : "=r"(t1) : "f"(v.y));
    asm("cvt.rna.tf32.f32 %0, %1;" : "=r"(t2) : "f"(v.z));
    asm("cvt.rna.tf32.f32 %0, %1;" : "=r"(t3) : "f"(v.w));

    int mtile = m >> 7;
    int mp = m & 127;
    int mf = mp >> 4;
    int rr = mp & 15;
    int kt = i >> 5;
    int kp = i & 31;
    int kk = kp >> 3;
    int hi = (kp & 7) >> 2;         // the 4 floats share kk and hi (i % 4 == 0)
    int lane0 = (rr & 7) * 4;
    int slot = ((rr >> 3) & 1) + 2 * hi;

    float* tile = g_At + (size_t)mtile * (NKT * TILE_FLOATS) + (size_t)kt * TILE_FLOATS;
    int base = (kk * 8 + mf) * 128 + lane0 * 4 + slot;
    tile[base]      = __uint_as_float(t0);
    tile[base + 4]  = __uint_as_float(t1);
    tile[base + 8]  = __uint_as_float(t2);
    tile[base + 12] = __uint_as_float(t3);
}

// ---------------------------------------------------------------------------
// GEMM: 128x128x32 tiles, 4 warps (2x2, warp tile 64x64), mma.sync tf32.
// Fragment-ordered SMEM (LDS.128 A / LDS.64 B), 3-stage cp.async,
// single barrier per k-tile.
// ---------------------------------------------------------------------------
__device__ __forceinline__ void mma_tf32(float* c, const uint32_t* a, const uint32_t* b) {
    asm volatile(
        "mma.sync.aligned.m16n8k8.row.col.f32.tf32.tf32.f32 "
        "{%0,%1,%2,%3}, {%4,%5,%6,%7}, {%8,%9}, {%0,%1,%2,%3};\n"
        : "+f"(c[0]), "+f"(c[1]), "+f"(c[2]), "+f"(c[3])
        : "r"(a[0]), "r"(a[1]), "r"(a[2]), "r"(a[3]),
          "r"(b[0]), "r"(b[1]));
}

__device__ __forceinline__ void load_stage(uint32_t sbase, const float* Asrc,
                                           const float* Bsrc, int kt, int buf, int tid) {
    uint32_t d = sbase + (uint32_t)buf * STAGE_BYTES + (uint32_t)tid * 16;
    const float* pa = Asrc + (size_t)kt * TILE_FLOATS + tid * 4;
    const float* pb = Bsrc + (size_t)kt * TILE_FLOATS + tid * 4;
#pragma unroll
    for (int i = 0; i < 8; i++) {
        asm volatile("cp.async.cg.shared.global [%0], [%1], 16;\n"
                     :: "r"(d + i * 2048), "l"(pa + i * 512));
        asm volatile("cp.async.cg.shared.global [%0], [%1], 16;\n"
                     :: "r"(d + 16384 + i * 2048), "l"(pb + i * 512));
    }
}

__global__ void __launch_bounds__(128, 2)
gemm_tf32_kernel(float* __restrict__ Out) {
    extern __shared__ float smem[];

    const int tid  = threadIdx.x;
    const int warp = tid >> 5;
    const int lane = tid & 31;
    const int wm = warp >> 1;              // 0..1 -> M offset wm*64
    const int wn = warp & 1;               // 0..1 -> N offset wn*64

    const float* Ag = g_At + (size_t)blockIdx.y * (NKT * TILE_FLOATS);
    const float* Bg = g_Bt + (size_t)blockIdx.x * (NKT * TILE_FLOATS);

    const uint32_t sbase = (uint32_t)__cvta_generic_to_shared(smem);

    float c[4][8][4];
#pragma unroll
    for (int i = 0; i < 4; i++)
#pragma unroll
        for (int j = 0; j < 8; j++)
#pragma unroll
            for (int k = 0; k < 4; k++) c[i][j][k] = 0.0f;

    load_stage(sbase, Ag, Bg, 0, 0, tid);
    asm volatile("cp.async.commit_group;\n" ::: "memory");
    load_stage(sbase, Ag, Bg, 1, 1, tid);
    asm volatile("cp.async.commit_group;\n" ::: "memory");

    for (int kt = 0; kt < NKT; kt++) {
        asm volatile("cp.async.wait_group 1;\n" ::: "memory");
        __syncthreads();

        if (kt + 2 < NKT)
            load_stage(sbase, Ag, Bg, kt + 2, (kt + 2) % STAGES, tid);
        asm volatile("cp.async.commit_group;\n" ::: "memory");

        const float* S = smem + (size_t)(kt % STAGES) * (STAGE_BYTES / 4);
        const float* A0 = S;                     // fragment-ordered A tile
        const float* B0 = S + TILE_FLOATS;       // fragment-ordered B tile

#pragma unroll
        for (int kk = 0; kk < 4; kk++) {
            uint32_t a[4][4];
            uint32_t b[8][2];
#pragma unroll
            for (int ma = 0; ma < 4; ma++) {
                const float4 v = *reinterpret_cast<const float4*>(
                    A0 + (kk * 8 + wm * 4 + ma) * 128 + lane * 4);
                a[ma][0] = __float_as_uint(v.x);
                a[ma][1] = __float_as_uint(v.y);
                a[ma][2] = __float_as_uint(v.z);
                a[ma][3] = __float_as_uint(v.w);
            }
#pragma unroll
            for (int nb = 0; nb < 8; nb++) {
                const float2 v = *reinterpret_cast<const float2*>(
                    B0 + (kk * 16 + wn * 8 + nb) * 64 + lane * 2);
                b[nb][0] = __float_as_uint(v.x);
                b[nb][1] = __float_as_uint(v.y);
            }
#pragma unroll
            for (int ma = 0; ma < 4; ma++)
#pragma unroll
                for (int nb = 0; nb < 8; nb++)
                    mma_tf32(c[ma][nb], a[ma], b[nb]);
        }
    }

    // epilogue
    float* Og = Out + (size_t)blockIdx.y * BM * OUT_F + blockIdx.x * BN;
#pragma unroll
    for (int ma = 0; ma < 4; ma++) {
#pragma unroll
        for (int nb = 0; nb < 8; nb++) {
            int r  = wm * 64 + ma * 16 + (lane >> 2);
            int cc = wn * 64 + nb * 8 + 2 * (lane & 3);
            *reinterpret_cast<float2*>(&Og[(size_t)r * OUT_F + cc]) =
                make_float2(c[ma][nb][0], c[ma][nb][1]);
            *reinterpret_cast<float2*>(&Og[(size_t)(r + 8) * OUT_F + cc]) =
                make_float2(c[ma][nb][2], c[ma][nb][3]);
        }
    }
}

// ---------------------------------------------------------------------------
extern "C" void kernel_launch(void* const* d_in, const int* in_sizes, int n_in,
                              void* d_out, int out_size) {
    const float* x      = (const float*)d_in[0];   // [M, 4096] fp32
    const int*   wp     = (const int*)d_in[1];     // [4096, 2048] int32 bytes
    const float* cent   = (const float*)d_in[2];   // [16]
    const float* scales = (const float*)d_in[3];   // [4096, 64]
    float* out = (float*)d_out;

    const int M = in_sizes[0] / IN_F;              // 8192

    int totalW = OUT_F * PACKED;
    dequant_kernel<<<(totalW + 255) / 256, 256>>>(wp, cent, scales);

    int totalX4 = M * (IN_F / 4);
    retile_x_kernel<<<(totalX4 + 255) / 256, 256>>>(x, M);

    cudaFuncSetAttribute(gemm_tf32_kernel,
                         cudaFuncAttributeMaxDynamicSharedMemorySize, SMEM_BYTES);
    dim3 grid(OUT_F / BN, M / BM);                 // (32, 64)
    gemm_tf32_kernel<<<grid, 128, SMEM_BYTES>>>(out);
}